// round 2
// baseline (speedup 1.0000x reference)
#include <cuda_runtime.h>
#include <cuda_bf16.h>

// Problem constants (fixed shapes from reference setup_inputs)
#define BB   8
#define FI   64
#define FIN  256
#define HW   4096
#define C8   8

// ---------------------------------------------------------------------------
// Scratch (device globals — no allocation allowed)
// ---------------------------------------------------------------------------
__device__ float g_psi[BB * FI * HW];     // relu(g1+x1)               8 MB
__device__ float g_att[BB * FI * FI];     // CAM raw gram
__device__ float g_attsm[BB * FI * FI];   // CAM softmax'd attention
__device__ float g_fb[BB * C8 * HW];      // PAM B proj
__device__ float g_fc[BB * C8 * HW];      // PAM C proj
__device__ float g_fd[BB * FI * HW];      // PAM D proj                8 MB
__device__ float g_cam[BB * FI * HW];     // CAM out (pre alpha/beta)  8 MB
__device__ float g_pam[BB * FI * HW];     // PAM out (pre alpha/beta)  8 MB

// ---------------------------------------------------------------------------
// Packed f32x2 helpers (Blackwell: fma.rn.f32x2 is 2x FFMA throughput)
// ---------------------------------------------------------------------------
__device__ __forceinline__ unsigned long long pk2(float f) {
    unsigned u = __float_as_uint(f);
    return ((unsigned long long)u << 32) | (unsigned long long)u;
}
__device__ __forceinline__ unsigned long long ffma2(unsigned long long a,
                                                    unsigned long long b,
                                                    unsigned long long c) {
    unsigned long long d;
    asm("fma.rn.f32x2 %0, %1, %2, %3;" : "=l"(d) : "l"(a), "l"(b), "l"(c));
    return d;
}
__device__ __forceinline__ unsigned long long fmul2_(unsigned long long a,
                                                     unsigned long long b) {
    unsigned long long d;
    asm("mul.rn.f32x2 %0, %1, %2;" : "=l"(d) : "l"(a), "l"(b));
    return d;
}

// ---------------------------------------------------------------------------
// K1: psi = relu(BN(Wg*g) + BN(Wx*x)) — GEMM with BN folded into weights.
// grid (HW/64, B), 256 threads. Tile: 64 out-ch x 64 px, k-chunks of 16.
// ---------------------------------------------------------------------------
__global__ void __launch_bounds__(256) k_psi(
    const float* __restrict__ g, const float* __restrict__ x,
    const float* __restrict__ Wg, const float* __restrict__ Wgb,
    const float* __restrict__ gga, const float* __restrict__ gbe,
    const float* __restrict__ gme, const float* __restrict__ gva,
    const float* __restrict__ Wx, const float* __restrict__ Wxb,
    const float* __restrict__ xga, const float* __restrict__ xbe,
    const float* __restrict__ xme, const float* __restrict__ xva)
{
    __shared__ float a_s[64][17];
    __shared__ float b_s[16][65];
    __shared__ float sgS[64], sxS[64], biasS[64];

    int b  = blockIdx.y;
    int p0 = blockIdx.x * 64;
    int t  = threadIdx.x;

    if (t < 64) {
        float sg = gga[t] * rsqrtf(gva[t] + 1e-5f);
        float sx = xga[t] * rsqrtf(xva[t] + 1e-5f);
        sgS[t] = sg; sxS[t] = sx;
        biasS[t] = (Wgb[t] - gme[t]) * sg + gbe[t]
                 + (Wxb[t] - xme[t]) * sx + xbe[t];
    }
    __syncthreads();

    int og = (t & 15) * 4;   // out-channel base (4 channels)
    int pg = (t >> 4) * 4;   // pixel base (4 pixels)
    float acc[4][4] = {};

    for (int half = 0; half < 2; half++) {
        const float* W  = half ? Wx : Wg;
        const float* in = half ? x  : g;
        const float* sc = half ? sxS : sgS;
        for (int k0 = 0; k0 < FIN; k0 += 16) {
            __syncthreads();
            for (int i = t; i < 64 * 16; i += 256) {
                int o = i >> 4, kk = i & 15;
                a_s[o][kk] = W[o * FIN + k0 + kk] * sc[o];
            }
            for (int i = t; i < 16 * 64; i += 256) {
                int kk = i >> 6, px = i & 63;
                b_s[kk][px] = in[((size_t)b * FIN + k0 + kk) * HW + p0 + px];
            }
            __syncthreads();
            #pragma unroll
            for (int kk = 0; kk < 16; kk++) {
                float av[4], bv[4];
                #pragma unroll
                for (int u = 0; u < 4; u++) av[u] = a_s[og + u][kk];
                #pragma unroll
                for (int v = 0; v < 4; v++) bv[v] = b_s[kk][pg + v];
                #pragma unroll
                for (int u = 0; u < 4; u++)
                    #pragma unroll
                    for (int v = 0; v < 4; v++)
                        acc[u][v] = fmaf(av[u], bv[v], acc[u][v]);
            }
        }
    }
    #pragma unroll
    for (int u = 0; u < 4; u++) {
        int o = og + u;
        #pragma unroll
        for (int v = 0; v < 4; v++) {
            int p = p0 + pg + v;
            g_psi[((size_t)b * FI + o) * HW + p] = fmaxf(acc[u][v] + biasS[o], 0.f);
        }
    }
}

// ---------------------------------------------------------------------------
// K2a: zero g_att
// ---------------------------------------------------------------------------
__global__ void k_zero() {
    int i = blockIdx.x * blockDim.x + threadIdx.x;
    if (i < BB * FI * FI) g_att[i] = 0.f;
}

// ---------------------------------------------------------------------------
// K2b: att[b,c,d] += sum over a 128-pixel chunk of psi[c,p]*psi[d,p]
// grid (32, B), 256 threads, atomic accumulation.
// ---------------------------------------------------------------------------
__global__ void __launch_bounds__(256) k_att()
{
    __shared__ float s[64][130];   // pad 130 -> bank (2c+p)%32, conflict-free
    int b  = blockIdx.y;
    int p0 = blockIdx.x * 128;
    int t  = threadIdx.x;

    for (int i = t; i < 64 * 128; i += 256) {
        int c = i >> 7, p = i & 127;
        s[c][p] = g_psi[((size_t)b * FI + c) * HW + p0 + p];
    }
    __syncthreads();

    int c  = t >> 2;
    int d0 = (t & 3) * 16;
    float acc[16] = {};
    for (int p = 0; p < 128; p++) {
        float a = s[c][p];
        #pragma unroll
        for (int r = 0; r < 16; r++) acc[r] = fmaf(a, s[d0 + r][p], acc[r]);
    }
    #pragma unroll
    for (int r = 0; r < 16; r++)
        atomicAdd(&g_att[((size_t)b * FI + c) * FI + d0 + r], acc[r]);
}

// ---------------------------------------------------------------------------
// K2c: CAM softmax. softmax(rowmax - att) == exp(rowmin - att)/sum.
// grid (B), 64 threads (one per row).
// ---------------------------------------------------------------------------
__global__ void k_attsm()
{
    int b = blockIdx.x, c = threadIdx.x;
    const float* row = &g_att[((size_t)b * FI + c) * FI];
    float mn = row[0];
    for (int d = 1; d < FI; d++) mn = fminf(mn, row[d]);
    float sum = 0.f;
    for (int d = 0; d < FI; d++) sum += __expf(mn - row[d]);
    float inv = 1.f / sum;
    float* dst = &g_attsm[((size_t)b * FI + c) * FI];
    for (int d = 0; d < FI; d++) dst[d] = __expf(mn - row[d]) * inv;
}

// ---------------------------------------------------------------------------
// K3: one pass over psi produces fb (8), fc (8), fd (64), camout (64):
//     144-row x 64-col weight (attsm is per-batch for camout rows).
// grid (HW/128, B), 256 threads, dynamic smem 69632 B.
// ---------------------------------------------------------------------------
__global__ void __launch_bounds__(256) k_proj(
    const float* __restrict__ pbw, const float* __restrict__ pbb,
    const float* __restrict__ pcw, const float* __restrict__ pcb,
    const float* __restrict__ pdw, const float* __restrict__ pdb)
{
    extern __shared__ float smp[];
    float* ps = smp;              // [64][128]
    float* w  = smp + 64 * 128;   // [144][64]
    __shared__ float bias_s[144];

    int b  = blockIdx.y;
    int p0 = blockIdx.x * 128;
    int t  = threadIdx.x;

    for (int i = t; i < 64 * 128; i += 256) {
        int k = i >> 7, px = i & 127;
        ps[i] = g_psi[((size_t)b * FI + k) * HW + p0 + px];
    }
    for (int i = t; i < 144 * 64; i += 256) {
        int r = i >> 6, k = i & 63;
        float v;
        if (r < 8)       v = pbw[r * FI + k];
        else if (r < 16) v = pcw[(r - 8) * FI + k];
        else if (r < 80) v = pdw[(r - 16) * FI + k];
        else             v = g_attsm[((size_t)b * FI + (r - 80)) * FI + k];
        w[i] = v;
    }
    if (t < 144) {
        float v;
        if (t < 8)       v = pbb[t];
        else if (t < 16) v = pcb[t - 8];
        else if (t < 80) v = pdb[t - 16];
        else             v = 0.f;
        bias_s[t] = v;
    }
    __syncthreads();

    int px = t & 127, half = t >> 7, r0 = half * 72;
    for (int rc = 0; rc < 9; rc++) {
        float acc[8];
        #pragma unroll
        for (int u = 0; u < 8; u++) acc[u] = bias_s[r0 + rc * 8 + u];
        for (int k = 0; k < 64; k++) {
            float bv = ps[k * 128 + px];
            #pragma unroll
            for (int u = 0; u < 8; u++)
                acc[u] = fmaf(w[(r0 + rc * 8 + u) * 64 + k], bv, acc[u]);
        }
        int p = p0 + px;
        #pragma unroll
        for (int u = 0; u < 8; u++) {
            int row = r0 + rc * 8 + u;
            if (row < 8)       g_fb[((size_t)b * C8 + row) * HW + p]        = acc[u];
            else if (row < 16) g_fc[((size_t)b * C8 + row - 8) * HW + p]    = acc[u];
            else if (row < 80) g_fd[((size_t)b * FI + row - 16) * HW + p]   = acc[u];
            else               g_cam[((size_t)b * FI + row - 80) * HW + p]  = acc[u];
        }
    }
}

// ---------------------------------------------------------------------------
// K4: PAM flash attention. Per batch: Q=fb^T [4096,8], K=fc^T [4096,8],
//     V=fd^T [4096,64]. Never materialize energy [4096,4096].
// One thread = one query; online softmax; f32x2 packed accumulation.
// grid (16, B), 256 threads, dynamic smem 75776 B (K tile + V tile).
// ---------------------------------------------------------------------------
#define FLASH_TJ 256
__global__ void __launch_bounds__(256) k_flash()
{
    extern __shared__ float sm[];
    float* ks2 = sm;                     // [256][8]  (j-major, float4-loadable)
    float* vs  = sm + FLASH_TJ * 8;      // [256][66] (pad 66: 2-way max on fill)

    int b = blockIdx.y;
    int t = threadIdx.x;
    int i = blockIdx.x * 256 + t;

    float q[8];
    #pragma unroll
    for (int k = 0; k < 8; k++) q[k] = g_fb[((size_t)b * C8 + k) * HW + i];

    float m = -1e30f, l = 0.f;
    unsigned long long acc[32];
    #pragma unroll
    for (int c = 0; c < 32; c++) acc[c] = 0ULL;

    for (int jt = 0; jt < HW; jt += FLASH_TJ) {
        __syncthreads();
        for (int idx = t; idx < 8 * FLASH_TJ; idx += 256) {
            int k = idx >> 8, j = idx & 255;
            ks2[j * 8 + k] = g_fc[((size_t)b * C8 + k) * HW + jt + j];
        }
        for (int idx = t; idx < 64 * FLASH_TJ; idx += 256) {
            int c = idx >> 8, j = idx & 255;
            vs[j * 66 + c] = g_fd[((size_t)b * FI + c) * HW + jt + j];
        }
        __syncthreads();

        // pass 1: tile max (dot only)
        float tm = m;
        #pragma unroll 4
        for (int j = 0; j < FLASH_TJ; j++) {
            const float4* kp = (const float4*)(ks2 + j * 8);
            float4 ka = kp[0], kb = kp[1];
            float e = q[0] * ka.x;
            e = fmaf(q[1], ka.y, e); e = fmaf(q[2], ka.z, e);
            e = fmaf(q[3], ka.w, e); e = fmaf(q[4], kb.x, e);
            e = fmaf(q[5], kb.y, e); e = fmaf(q[6], kb.z, e);
            e = fmaf(q[7], kb.w, e);
            tm = fmaxf(tm, e);
        }
        // rescale running state once per tile
        float sc = __expf(m - tm);
        l *= sc;
        unsigned long long s2 = pk2(sc);
        #pragma unroll
        for (int c = 0; c < 32; c++) acc[c] = fmul2_(acc[c], s2);
        m = tm;

        // pass 2: exp + accumulate V (packed f32x2)
        #pragma unroll 2
        for (int j = 0; j < FLASH_TJ; j++) {
            const float4* kp = (const float4*)(ks2 + j * 8);
            float4 ka = kp[0], kb = kp[1];
            float e = q[0] * ka.x;
            e = fmaf(q[1], ka.y, e); e = fmaf(q[2], ka.z, e);
            e = fmaf(q[3], ka.w, e); e = fmaf(q[4], kb.x, e);
            e = fmaf(q[5], kb.y, e); e = fmaf(q[6], kb.z, e);
            e = fmaf(q[7], kb.w, e);
            float p = __expf(e - m);
            l += p;
            unsigned long long p2 = pk2(p);
            const unsigned long long* vp = (const unsigned long long*)(vs + j * 66);
            #pragma unroll
            for (int c = 0; c < 32; c++) acc[c] = ffma2(p2, vp[c], acc[c]);
        }
    }

    float inv = 1.f / l;
    #pragma unroll
    for (int c = 0; c < 32; c++) {
        float lo = __uint_as_float((unsigned)(acc[c] & 0xffffffffULL));
        float hi = __uint_as_float((unsigned)(acc[c] >> 32));
        g_pam[((size_t)b * FI + 2 * c) * HW + i]     = lo * inv;
        g_pam[((size_t)b * FI + 2 * c + 1) * HW + i] = hi * inv;
    }
}

// ---------------------------------------------------------------------------
// K5: gate = BN(conv1x1(cam*pam, psi_w)); out = x * sigmoid(gate)
// grid (16, B), 256 threads (one pixel each for the reduction phase).
// ---------------------------------------------------------------------------
__global__ void __launch_bounds__(256) k_final(
    const float* __restrict__ x,
    const float* __restrict__ psiw, const float* __restrict__ psib,
    const float* __restrict__ pga,  const float* __restrict__ pbe,
    const float* __restrict__ pme,  const float* __restrict__ pva,
    const float* __restrict__ alpha, const float* __restrict__ camb,
    float* __restrict__ out)
{
    __shared__ float das[256];
    __shared__ float wsh[64];
    int b  = blockIdx.y;
    int p0 = blockIdx.x * 256;
    int t  = threadIdx.x;

    if (t < 64) wsh[t] = psiw[t];
    __syncthreads();

    float a  = alpha[0];
    float be = camb[0];
    int p = p0 + t;
    float s = 0.f;
    for (int c = 0; c < 64; c++) {
        size_t idx = ((size_t)b * FI + c) * HW + p;
        float ps = g_psi[idx];
        float co = g_cam[idx];
        float po = g_pam[idx];
        s = fmaf(wsh[c], (fmaf(be, co, ps)) * (fmaf(a, po, ps)), s);
    }
    float inv = pga[0] * rsqrtf(pva[0] + 1e-5f);
    float y = (s + psib[0] - pme[0]) * inv + pbe[0];
    das[t] = 1.f / (1.f + __expf(-y));
    __syncthreads();

    for (int idx = t; idx < 256 * 256; idx += 256) {
        int C = idx >> 8, pp = idx & 255;
        size_t gi = ((size_t)b * FIN + C) * HW + p0 + pp;
        out[gi] = x[gi] * das[pp];
    }
}

// ---------------------------------------------------------------------------
// launch
// ---------------------------------------------------------------------------
extern "C" void kernel_launch(void* const* d_in, const int* in_sizes, int n_in,
                              void* d_out, int out_size)
{
    const float* g    = (const float*)d_in[0];
    const float* x    = (const float*)d_in[1];
    const float* Wg_w = (const float*)d_in[2];
    const float* Wg_b = (const float*)d_in[3];
    const float* bngg = (const float*)d_in[4];
    const float* bngb = (const float*)d_in[5];
    const float* bngm = (const float*)d_in[6];
    const float* bngv = (const float*)d_in[7];
    const float* Wx_w = (const float*)d_in[8];
    const float* Wx_b = (const float*)d_in[9];
    const float* bnxg = (const float*)d_in[10];
    const float* bnxb = (const float*)d_in[11];
    const float* bnxm = (const float*)d_in[12];
    const float* bnxv = (const float*)d_in[13];
    const float* psiw = (const float*)d_in[14];
    const float* psib = (const float*)d_in[15];
    const float* bnpg = (const float*)d_in[16];
    const float* bnpb = (const float*)d_in[17];
    const float* bnpm = (const float*)d_in[18];
    const float* bnpv = (const float*)d_in[19];
    const float* pb_w = (const float*)d_in[20];
    const float* pb_b = (const float*)d_in[21];
    const float* pc_w = (const float*)d_in[22];
    const float* pc_b = (const float*)d_in[23];
    const float* pd_w = (const float*)d_in[24];
    const float* pd_b = (const float*)d_in[25];
    const float* alpha = (const float*)d_in[26];
    const float* camb  = (const float*)d_in[27];
    float* out = (float*)d_out;

    const int PROJ_SMEM  = (64 * 128 + 144 * 64) * 4;          // 69632 B
    const int FLASH_SMEM = (FLASH_TJ * 8 + FLASH_TJ * 66) * 4; // 75776 B
    cudaFuncSetAttribute(k_proj,  cudaFuncAttributeMaxDynamicSharedMemorySize, PROJ_SMEM);
    cudaFuncSetAttribute(k_flash, cudaFuncAttributeMaxDynamicSharedMemorySize, FLASH_SMEM);

    k_psi<<<dim3(HW / 64, BB), 256>>>(g, x,
        Wg_w, Wg_b, bngg, bngb, bngm, bngv,
        Wx_w, Wx_b, bnxg, bnxb, bnxm, bnxv);
    k_zero<<<(BB * FI * FI + 255) / 256, 256>>>();
    k_att<<<dim3(HW / 128, BB), 256>>>();
    k_attsm<<<BB, 64>>>();
    k_proj<<<dim3(HW / 128, BB), 256, PROJ_SMEM>>>(pb_w, pb_b, pc_w, pc_b, pd_w, pd_b);
    k_flash<<<dim3(HW / 256, BB), 256, FLASH_SMEM>>>();
    k_final<<<dim3(HW / 256, BB), 256>>>(x, psiw, psib, bnpg, bnpb, bnpm, bnpv,
                                         alpha, camb, out);
}